// round 10
// baseline (speedup 1.0000x reference)
#include <cuda_runtime.h>
#include <cstdint>

#define SS    224
#define PP    30
#define CROPV 164
#define BB    16
#define TT    16
#define J4    56                       // float4 per row
#define ROWS_PER_TILE 16
#define TILES_PER_FRAME 14             // 224 / 16
#define TILE_F4   896                  // 16 * 56 float4
#define TILE_BYTES 14336
#define THREADS   128
#define F4_PER_THREAD 7                // 896 / 128
#define FRAME_FLOATS (SS * SS)         // 50176
#define NCTA (BB * 3 * TILES_PER_FRAME) // 672

__device__ __forceinline__ uint32_t smem_u32(const void* p) {
    return (uint32_t)__cvta_generic_to_shared(p);
}

// bilinear prompt value at (i, j4) — identical math to the validated kernels
__device__ __forceinline__ float4 compute_pv(
    int i, int j4, int cam, int c, int orr, int od,
    const float* __restrict__ pu, const float* __restrict__ pd,
    const float* __restrict__ pl, const float* __restrict__ pr)
{
    int off_l = 2 * PP - orr;   // [30,59]
    int off_u = 2 * PP - od;    // [30,59]
    int j = j4 * 4;
    float4 pv;

    if (i < off_u) {
        float scale = 60.0f / (float)off_u;
        float f = fmaxf(((float)i + 0.5f) * scale - 0.5f, 0.0f);
        int   r0 = (int)floorf(f);
        float w  = f - (float)r0;
        int   r1 = min(r0 + 1, 59);
        const float4* row0 = (const float4*)(pu + ((size_t)(cam * 3 + c) * 60 + r0) * SS) + j4;
        const float4* row1 = (const float4*)(pu + ((size_t)(cam * 3 + c) * 60 + r1) * SS) + j4;
        float4 a = __ldg(row0);
        float4 d = __ldg(row1);
        float om = 1.0f - w;
        pv.x = a.x * om + d.x * w; pv.y = a.y * om + d.y * w;
        pv.z = a.z * om + d.z * w; pv.w = a.w * om + d.w * w;
    } else if (i >= SS - od) {
        float scale = 30.0f / (float)od;
        float pos = (float)(i - (SS - od));
        float f = fmaxf((pos + 0.5f) * scale - 0.5f, 0.0f);
        int   r0 = (int)floorf(f);
        float w  = f - (float)r0;
        int   r1 = min(r0 + 1, 29);
        const float4* row0 = (const float4*)(pd + ((size_t)(cam * 3 + c) * 30 + r0) * SS) + j4;
        const float4* row1 = (const float4*)(pd + ((size_t)(cam * 3 + c) * 30 + r1) * SS) + j4;
        float4 a = __ldg(row0);
        float4 d = __ldg(row1);
        float om = 1.0f - w;
        pv.x = a.x * om + d.x * w; pv.y = a.y * om + d.y * w;
        pv.z = a.z * om + d.z * w; pv.w = a.w * om + d.w * w;
    } else {
        int r = i - off_u;
        const float* lrow = pl + ((size_t)(cam * 3 + c) * CROPV + r) * (2 * PP);
        const float* rrow = pr + ((size_t)(cam * 3 + c) * CROPV + r) * PP;
        float vals[4];
        #pragma unroll
        for (int k = 0; k < 4; k++) {
            int jj = j + k;
            float v = 0.0f;
            if (jj < off_l) {
                float scale = 60.0f / (float)off_l;
                float f = fmaxf(((float)jj + 0.5f) * scale - 0.5f, 0.0f);
                int   c0 = (int)floorf(f);
                float w  = f - (float)c0;
                int   c1 = min(c0 + 1, 59);
                v = __ldg(lrow + c0) * (1.0f - w) + __ldg(lrow + c1) * w;
            } else if (jj >= SS - orr) {
                float scale = 30.0f / (float)orr;
                float pos = (float)(jj - (SS - orr));
                float f = fmaxf((pos + 0.5f) * scale - 0.5f, 0.0f);
                int   c0 = (int)floorf(f);
                float w  = f - (float)c0;
                int   c1 = min(c0 + 1, 29);
                v = __ldg(rrow + c0) * (1.0f - w) + __ldg(rrow + c1) * w;
            }
            vals[k] = v;
        }
        pv.x = vals[0]; pv.y = vals[1]; pv.z = vals[2]; pv.w = vals[3];
    }
    return pv;
}

__global__ __launch_bounds__(THREADS) void prompter_bulk_kernel(
    const float* __restrict__ x,
    const float* __restrict__ pu,
    const float* __restrict__ pd,
    const float* __restrict__ pl,
    const float* __restrict__ pr,
    const int*   __restrict__ cams,
    const int*   __restrict__ offs_r,
    const int*   __restrict__ offs_d,
    float* __restrict__ out)
{
    __shared__ __align__(128) float4 buf[2][TILE_F4];       // 2 x 14336 B
    __shared__ __align__(8) unsigned long long mbar[2];

    int tid  = threadIdx.x;
    int cta  = blockIdx.x;
    int tile = cta % TILES_PER_FRAME;
    int bc   = cta / TILES_PER_FRAME;
    int b    = bc / 3;
    int c    = bc % 3;

    int cam = cams[b];
    int orr = offs_r[b];
    int od  = offs_d[b];

    // prompt values for this thread's 7 float4 slots, computed once
    float4 pv[F4_PER_THREAD];
    #pragma unroll
    for (int u = 0; u < F4_PER_THREAD; u++) {
        int idx = tid + THREADS * u;               // [0, 896)
        int i   = tile * ROWS_PER_TILE + idx / J4;
        int jj4 = idx % J4;
        pv[u] = compute_pv(i, jj4, cam, c, orr, od, pu, pd, pl, pr);
    }

    uint32_t mb0 = smem_u32(&mbar[0]);
    uint32_t mb1 = smem_u32(&mbar[1]);
    if (tid == 0) {
        asm volatile("mbarrier.init.shared.b64 [%0], %1;" :: "r"(mb0), "r"(1) : "memory");
        asm volatile("mbarrier.init.shared.b64 [%0], %1;" :: "r"(mb1), "r"(1) : "memory");
    }
    __syncthreads();

    size_t base = ((size_t)bc * TT) * FRAME_FLOATS + (size_t)tile * (ROWS_PER_TILE * SS);
    const float* xbase = x + base;
    float*       obase = out + base;

    uint32_t bufu[2] = { smem_u32(&buf[0][0]), smem_u32(&buf[1][0]) };
    uint32_t mbu[2]  = { mb0, mb1 };

    // kick off t = 0
    if (tid == 0) {
        asm volatile("mbarrier.arrive.expect_tx.shared.b64 _, [%0], %1;"
                     :: "r"(mbu[0]), "r"(TILE_BYTES) : "memory");
        asm volatile("cp.async.bulk.shared::cta.global.mbarrier::complete_tx::bytes [%0], [%1], %2, [%3];"
                     :: "r"(bufu[0]), "l"(xbase), "r"(TILE_BYTES), "r"(mbu[0]) : "memory");
    }

    int ph[2] = {0, 0};
    for (int t = 0; t < TT; t++) {
        int p = t & 1;
        // prefetch next frame into the other buffer (consumed at t-1, bar'ed)
        if (t + 1 < TT && tid == 0) {
            asm volatile("mbarrier.arrive.expect_tx.shared.b64 _, [%0], %1;"
                         :: "r"(mbu[1 - p]), "r"(TILE_BYTES) : "memory");
            asm volatile("cp.async.bulk.shared::cta.global.mbarrier::complete_tx::bytes [%0], [%1], %2, [%3];"
                         :: "r"(bufu[1 - p]), "l"(xbase + (size_t)(t + 1) * FRAME_FLOATS),
                            "r"(TILE_BYTES), "r"(mbu[1 - p]) : "memory");
        }
        // wait for buffer p
        {
            uint32_t done = 0;
            while (!done) {
                asm volatile(
                    "{\n\t.reg .pred pd;\n\t"
                    "mbarrier.try_wait.parity.acquire.cta.shared::cta.b64 pd, [%1], %2;\n\t"
                    "selp.b32 %0, 1, 0, pd;\n\t}"
                    : "=r"(done) : "r"(mbu[p]), "r"((uint32_t)ph[p]) : "memory");
            }
            ph[p] ^= 1;
        }
        // add prompt, stream out
        float4* ofr = (float4*)(obase + (size_t)t * FRAME_FLOATS);
        #pragma unroll
        for (int u = 0; u < F4_PER_THREAD; u++) {
            float4 v = buf[p][tid + THREADS * u];
            v.x += pv[u].x; v.y += pv[u].y; v.z += pv[u].z; v.w += pv[u].w;
            ofr[tid + THREADS * u] = v;
        }
        __syncthreads();   // buffer p fully consumed before it is refilled at t+2
    }
}

extern "C" void kernel_launch(void* const* d_in, const int* in_sizes, int n_in,
                              void* d_out, int out_size) {
    const float* x   = (const float*)d_in[0];
    const float* pu  = (const float*)d_in[1];
    const float* pd  = (const float*)d_in[2];
    const float* pl  = (const float*)d_in[3];
    const float* pr  = (const float*)d_in[4];
    const int*   cam = (const int*)d_in[5];
    const int*   orr = (const int*)d_in[6];
    const int*   od  = (const int*)d_in[7];
    float* out = (float*)d_out;

    prompter_bulk_kernel<<<NCTA, THREADS>>>(x, pu, pd, pl, pr, cam, orr, od, out);
}

// round 12
// speedup vs baseline: 1.1524x; 1.1524x over previous
#include <cuda_runtime.h>

#define SS   224
#define PP   30
#define CROPV 164
#define BB   16
#define TT   16
#define TG   4                             // frames per thread
#define NTG  (TT / TG)                     // 4 t-groups (gridDim.y)
#define J4   (SS / 4)                      // 56 float4 per row
#define SPATIAL_THREADS (BB * 3 * SS * J4) // 602112 = 2352 * 256

__global__ __launch_bounds__(256) void prompter_add_kernel(
    const float* __restrict__ x,        // [B,3,T,S,S]
    const float* __restrict__ pu,       // [3,3,2P,S]
    const float* __restrict__ pd,       // [3,3,P,S]
    const float* __restrict__ pl,       // [3,3,CROP,2P]
    const float* __restrict__ pr,       // [3,3,CROP,P]
    const int*   __restrict__ cams,     // [B]
    const int*   __restrict__ offs_r,   // [B]
    const int*   __restrict__ offs_d,   // [B]
    float* __restrict__ out)            // [B,3,T,S,S]
{
    int tid = blockIdx.x * blockDim.x + threadIdx.x;
    int tg  = blockIdx.y;                  // t-group: no per-thread div/mod

    int j4 = tid % J4;
    int i  = (tid / J4) % SS;
    int c  = (tid / (J4 * SS)) % 3;
    int b  =  tid / (J4 * SS * 3);
    int j  = j4 * 4;

    int cam = cams[b];
    int orr = offs_r[b];
    int od  = offs_d[b];
    int off_l = 2 * PP - orr;   // [30,59]
    int off_u = 2 * PP - od;    // [30,59]

    float4 pv;

    if (i < off_u) {
        // top band: vertical interp between two rows of pad_up (in_size=60)
        float scale = 60.0f / (float)off_u;
        float f = fmaxf(((float)i + 0.5f) * scale - 0.5f, 0.0f);
        int   r0 = (int)floorf(f);
        float w  = f - (float)r0;
        int   r1 = min(r0 + 1, 59);
        const float4* row0 = (const float4*)(pu + ((size_t)(cam * 3 + c) * 60 + r0) * SS) + j4;
        const float4* row1 = (const float4*)(pu + ((size_t)(cam * 3 + c) * 60 + r1) * SS) + j4;
        float4 a = __ldg(row0);
        float4 d = __ldg(row1);
        float om = 1.0f - w;
        pv.x = a.x * om + d.x * w;
        pv.y = a.y * om + d.y * w;
        pv.z = a.z * om + d.z * w;
        pv.w = a.w * om + d.w * w;
    } else if (i >= SS - od) {
        // bottom band: vertical interp between two rows of pad_down (in_size=30)
        float scale = 30.0f / (float)od;
        float pos = (float)(i - (SS - od));
        float f = fmaxf((pos + 0.5f) * scale - 0.5f, 0.0f);
        int   r0 = (int)floorf(f);
        float w  = f - (float)r0;
        int   r1 = min(r0 + 1, 29);
        const float4* row0 = (const float4*)(pd + ((size_t)(cam * 3 + c) * 30 + r0) * SS) + j4;
        const float4* row1 = (const float4*)(pd + ((size_t)(cam * 3 + c) * 30 + r1) * SS) + j4;
        float4 a = __ldg(row0);
        float4 d = __ldg(row1);
        float om = 1.0f - w;
        pv.x = a.x * om + d.x * w;
        pv.y = a.y * om + d.y * w;
        pv.z = a.z * om + d.z * w;
        pv.w = a.w * om + d.w * w;
    } else {
        // middle band: horizontal interp (left pad / zero / right pad), row r
        int r = i - off_u;                 // [0, CROP)
        const float* lrow = pl + ((size_t)(cam * 3 + c) * CROPV + r) * (2 * PP);
        const float* rrow = pr + ((size_t)(cam * 3 + c) * CROPV + r) * PP;
        float vals[4];
        #pragma unroll
        for (int k = 0; k < 4; k++) {
            int jj = j + k;
            float v = 0.0f;
            if (jj < off_l) {
                float scale = 60.0f / (float)off_l;
                float f = fmaxf(((float)jj + 0.5f) * scale - 0.5f, 0.0f);
                int   c0 = (int)floorf(f);
                float w  = f - (float)c0;
                int   c1 = min(c0 + 1, 59);
                v = __ldg(lrow + c0) * (1.0f - w) + __ldg(lrow + c1) * w;
            } else if (jj >= SS - orr) {
                float scale = 30.0f / (float)orr;
                float pos = (float)(jj - (SS - orr));
                float f = fmaxf((pos + 0.5f) * scale - 0.5f, 0.0f);
                int   c0 = (int)floorf(f);
                float w  = f - (float)c0;
                int   c1 = min(c0 + 1, 29);
                v = __ldg(rrow + c0) * (1.0f - w) + __ldg(rrow + c1) * w;
            }
            vals[k] = v;
        }
        pv.x = vals[0]; pv.y = vals[1]; pv.z = vals[2]; pv.w = vals[3];
    }

    // out[b,c,t,i,j] = x[b,c,t,i,j] + pv for t in [tg*TG, tg*TG+TG)
    size_t base = ((((size_t)b * 3 + c) * TT) + (size_t)tg * TG) * (size_t)(SS * SS)
                + (size_t)i * SS + (size_t)j;
    const float4* xin  = (const float4*)(x + base);
    float4*       oout = (float4*)(out + base);
    const int stride4 = (SS * SS) / 4;   // float4 stride between frames

    #pragma unroll
    for (int t = 0; t < TG; t++) {
        float4 xv = __ldg(xin + (size_t)t * stride4);
        xv.x += pv.x; xv.y += pv.y; xv.z += pv.z; xv.w += pv.w;
        oout[(size_t)t * stride4] = xv;
    }
}

extern "C" void kernel_launch(void* const* d_in, const int* in_sizes, int n_in,
                              void* d_out, int out_size) {
    const float* x   = (const float*)d_in[0];
    const float* pu  = (const float*)d_in[1];
    const float* pd  = (const float*)d_in[2];
    const float* pl  = (const float*)d_in[3];
    const float* pr  = (const float*)d_in[4];
    const int*   cam = (const int*)d_in[5];
    const int*   orr = (const int*)d_in[6];
    const int*   od  = (const int*)d_in[7];
    float* out = (float*)d_out;

    dim3 grid(SPATIAL_THREADS / 256, NTG);   // (2352, 4)
    prompter_add_kernel<<<grid, 256>>>(x, pu, pd, pl, pr, cam, orr, od, out);
}

// round 13
// speedup vs baseline: 1.1988x; 1.0402x over previous
#include <cuda_runtime.h>

#define SS   224
#define PP   30
#define CROPV 164
#define BB   16
#define TT   16
#define TG   4                             // frames per thread
#define NTG  (TT / TG)                     // 4 t-groups
#define J4   (SS / 4)                      // 56 float4 per row
#define TOTAL_THREADS (BB * 3 * SS * J4 * NTG)   // 2408448 = 9408 * 256

__global__ __launch_bounds__(256) void prompter_add_kernel(
    const float* __restrict__ x,        // [B,3,T,S,S]
    const float* __restrict__ pu,       // [3,3,2P,S]
    const float* __restrict__ pd,       // [3,3,P,S]
    const float* __restrict__ pl,       // [3,3,CROP,2P]
    const float* __restrict__ pr,       // [3,3,CROP,P]
    const int*   __restrict__ cams,     // [B]
    const int*   __restrict__ offs_r,   // [B]
    const int*   __restrict__ offs_d,   // [B]
    float* __restrict__ out)            // [B,3,T,S,S]
{
    int tid = blockIdx.x * blockDim.x + threadIdx.x;

    int j4 = tid % J4;
    int i  = (tid / J4) % SS;
    int c  = (tid / (J4 * SS)) % 3;
    int b  = (tid / (J4 * SS * 3)) % BB;
    int tg =  tid / (J4 * SS * 3 * BB);
    int j  = j4 * 4;

    int cam = cams[b];
    int orr = offs_r[b];
    int od  = offs_d[b];
    int off_l = 2 * PP - orr;   // [30,59]
    int off_u = 2 * PP - od;    // [30,59]

    float4 pv;

    if (i < off_u) {
        // top band: vertical interp between two rows of pad_up (in_size=60)
        float scale = 60.0f / (float)off_u;
        float f = fmaxf(((float)i + 0.5f) * scale - 0.5f, 0.0f);
        int   r0 = (int)floorf(f);
        float w  = f - (float)r0;
        int   r1 = min(r0 + 1, 59);
        const float4* row0 = (const float4*)(pu + ((size_t)(cam * 3 + c) * 60 + r0) * SS) + j4;
        const float4* row1 = (const float4*)(pu + ((size_t)(cam * 3 + c) * 60 + r1) * SS) + j4;
        float4 a = __ldg(row0);
        float4 d = __ldg(row1);
        float om = 1.0f - w;
        pv.x = a.x * om + d.x * w;
        pv.y = a.y * om + d.y * w;
        pv.z = a.z * om + d.z * w;
        pv.w = a.w * om + d.w * w;
    } else if (i >= SS - od) {
        // bottom band: vertical interp between two rows of pad_down (in_size=30)
        float scale = 30.0f / (float)od;
        float pos = (float)(i - (SS - od));
        float f = fmaxf((pos + 0.5f) * scale - 0.5f, 0.0f);
        int   r0 = (int)floorf(f);
        float w  = f - (float)r0;
        int   r1 = min(r0 + 1, 29);
        const float4* row0 = (const float4*)(pd + ((size_t)(cam * 3 + c) * 30 + r0) * SS) + j4;
        const float4* row1 = (const float4*)(pd + ((size_t)(cam * 3 + c) * 30 + r1) * SS) + j4;
        float4 a = __ldg(row0);
        float4 d = __ldg(row1);
        float om = 1.0f - w;
        pv.x = a.x * om + d.x * w;
        pv.y = a.y * om + d.y * w;
        pv.z = a.z * om + d.z * w;
        pv.w = a.w * om + d.w * w;
    } else {
        // middle band: horizontal interp (left pad / zero / right pad), row r
        int r = i - off_u;                 // [0, CROP)
        const float* lrow = pl + ((size_t)(cam * 3 + c) * CROPV + r) * (2 * PP);
        const float* rrow = pr + ((size_t)(cam * 3 + c) * CROPV + r) * PP;
        float vals[4];
        #pragma unroll
        for (int k = 0; k < 4; k++) {
            int jj = j + k;
            float v = 0.0f;
            if (jj < off_l) {
                float scale = 60.0f / (float)off_l;
                float f = fmaxf(((float)jj + 0.5f) * scale - 0.5f, 0.0f);
                int   c0 = (int)floorf(f);
                float w  = f - (float)c0;
                int   c1 = min(c0 + 1, 59);
                v = __ldg(lrow + c0) * (1.0f - w) + __ldg(lrow + c1) * w;
            } else if (jj >= SS - orr) {
                float scale = 30.0f / (float)orr;
                float pos = (float)(jj - (SS - orr));
                float f = fmaxf((pos + 0.5f) * scale - 0.5f, 0.0f);
                int   c0 = (int)floorf(f);
                float w  = f - (float)c0;
                int   c1 = min(c0 + 1, 29);
                v = __ldg(rrow + c0) * (1.0f - w) + __ldg(rrow + c1) * w;
            }
            vals[k] = v;
        }
        pv.x = vals[0]; pv.y = vals[1]; pv.z = vals[2]; pv.w = vals[3];
    }

    // out[b,c,t,i,j] = x[b,c,t,i,j] + pv for t in [tg*TG, tg*TG+TG)
    size_t base = ((((size_t)b * 3 + c) * TT) + (size_t)tg * TG) * (size_t)(SS * SS)
                + (size_t)i * SS + (size_t)j;
    const float4* xin  = (const float4*)(x + base);
    float4*       oout = (float4*)(out + base);
    const int stride4 = (SS * SS) / 4;   // float4 stride between frames

    #pragma unroll
    for (int t = 0; t < TG; t++) {
        float4 xv = __ldg(xin + (size_t)t * stride4);
        xv.x += pv.x; xv.y += pv.y; xv.z += pv.z; xv.w += pv.w;
        oout[(size_t)t * stride4] = xv;
    }
}

extern "C" void kernel_launch(void* const* d_in, const int* in_sizes, int n_in,
                              void* d_out, int out_size) {
    const float* x   = (const float*)d_in[0];
    const float* pu  = (const float*)d_in[1];
    const float* pd  = (const float*)d_in[2];
    const float* pl  = (const float*)d_in[3];
    const float* pr  = (const float*)d_in[4];
    const int*   cam = (const int*)d_in[5];
    const int*   orr = (const int*)d_in[6];
    const int*   od  = (const int*)d_in[7];
    float* out = (float*)d_out;

    const int threads = 256;
    const int blocks  = TOTAL_THREADS / threads;  // 9408
    prompter_add_kernel<<<blocks, threads>>>(x, pu, pd, pl, pr, cam, orr, od, out);
}